// round 17
// baseline (speedup 1.0000x reference)
#include <cuda_runtime.h>
#include <cuda_fp16.h>
#include <float.h>
#include <stdint.h>

#define NCODES   4096
#define CDIM     64
#define NTOK     65536
#define HW       4096
#define M_TILE   128
#define N_CHUNK  256
#define NCHUNKS  16
#define THREADS  256
#define SCALE    64.0f
#define DESC     2.44140625e-4f   // 1/4096
#define NEG2DESC (-4.8828125e-4f) // -2/4096

#define B_STRIDE 144      // 64 halves (128B) + 16B pad -> conflict-free ldmatrix
#define ESQ_TAIL 36864    // esq tail offset inside each BH buffer (256 floats)

// ---- main kernel smem (per CTA 100352 -> 2 CTAs/SM) ----
#define OFF_AH     0        // 128*144 fp16 z-hi tile
#define OFF_BH0    18432    // 36864 data + 1024 esq
#define OFF_BH1    56320    // 36864 data + 1024 esq
#define OFF_SB     94208    // submin buf: 128 tok x 48B (16 cols + pad)
#define SMEM_MAIN  100352

// ---- resolve kernel smem ----
#define SMEM_RES   34304    // zs[64*130]f + sidx[128] + eps[128]

__device__ float  g_esq[NCODES];               // ||e||^2 (UNscaled)
__device__ __half g_embh[NCODES * CDIM];       // hi(e*64)
__device__ __half g_smin[(size_t)NTOK * 256];  // per (token, 16-code group) min, descaled
__device__ int    g_Eh2 = 0;                   // max_c ||hi_e||^2 (scaled), float bits
__device__ int    g_El2 = 0;                   // max_c ||lo_e||^2 (scaled), float bits

__device__ __forceinline__ uint32_t smem_u32(const void* p) {
    uint32_t a;
    asm("{ .reg .u64 t; cvta.to.shared.u64 t, %1; cvt.u32.u64 %0, t; }" : "=r"(a) : "l"(p));
    return a;
}
__device__ __forceinline__ void cp16(uint32_t dst, const void* src) {
    asm volatile("cp.async.cg.shared.global [%0], [%1], 16;" :: "r"(dst), "l"(src));
}
__device__ __forceinline__ void cp_commit() { asm volatile("cp.async.commit_group;"); }
template <int N>
__device__ __forceinline__ void cp_wait() { asm volatile("cp.async.wait_group %0;" :: "n"(N)); }

__device__ __forceinline__ void mma16816(float* c, const uint32_t* a, uint32_t b0, uint32_t b1) {
    asm volatile(
        "mma.sync.aligned.m16n8k16.row.col.f32.f16.f16.f32 "
        "{%0,%1,%2,%3}, {%4,%5,%6,%7}, {%8,%9}, {%0,%1,%2,%3};"
        : "+f"(c[0]), "+f"(c[1]), "+f"(c[2]), "+f"(c[3])
        : "r"(a[0]), "r"(a[1]), "r"(a[2]), "r"(a[3]), "r"(b0), "r"(b1));
}
__device__ __forceinline__ void ldmx4(uint32_t& r0, uint32_t& r1, uint32_t& r2, uint32_t& r3,
                                      uint32_t a) {
    asm volatile("ldmatrix.sync.aligned.m8n8.x4.shared.b16 {%0,%1,%2,%3}, [%4];"
        : "=r"(r0), "=r"(r1), "=r"(r2), "=r"(r3) : "r"(a));
}
__device__ __forceinline__ uint32_t pack2h(float v0, float v1) {
    __half h0 = __float2half_rn(v0);
    __half h1 = __float2half_rn(v1);
    return (uint32_t)__half_as_ushort(h0) | ((uint32_t)__half_as_ushort(h1) << 16);
}

// prep: hi fp16 codebook (scaled), esq (unscaled), max hi/lo norms. one warp per code.
__global__ void prep_kernel(const float* __restrict__ emb) {
    int warp = (blockIdx.x * blockDim.x + threadIdx.x) >> 5;
    int lane = threadIdx.x & 31;
    if (warp >= NCODES) return;
    const float* row = emb + (size_t)warp * CDIM;
    float v0 = row[lane] * SCALE, v1 = row[lane + 32] * SCALE;
    __half h0 = __float2half_rn(v0), h1 = __float2half_rn(v1);
    g_embh[warp * CDIM + lane]      = h0;
    g_embh[warp * CDIM + lane + 32] = h1;
    float hf0 = __half2float(h0), hf1 = __half2float(h1);
    float l0 = v0 - hf0, l1 = v1 - hf1;
    float s  = v0 * v0 + v1 * v1;   // scaled; store *DESC -> unscaled
    float hs = hf0 * hf0 + hf1 * hf1;
    float ls = l0 * l0 + l1 * l1;
    #pragma unroll
    for (int off = 16; off; off >>= 1) {
        s  += __shfl_xor_sync(0xffffffffu, s,  off);
        hs += __shfl_xor_sync(0xffffffffu, hs, off);
        ls += __shfl_xor_sync(0xffffffffu, ls, off);
    }
    if (lane == 0) {
        g_esq[warp] = s * DESC;                  // ||e||^2 unscaled
        atomicMax(&g_Eh2, __float_as_int(hs));
        atomicMax(&g_El2, __float_as_int(ls));
    }
}

// ---- stage 1: 1-pass hi*hi GEMM (m32 warp tile), 16-code group mins -> g_smin ----
__global__ __launch_bounds__(THREADS, 2)
void vq_main(const float* __restrict__ z) {
    extern __shared__ char sm[];
    const uint32_t sb = smem_u32(sm);
    const int tid  = threadIdx.x;
    const int lane = tid & 31;
    const int wid  = tid >> 5;
    const int grp  = lane >> 2;     // 0..7
    const int tid4 = lane & 3;      // 0..3
    const int mg   = wid >> 1;      // 0..3 : token rows mg*32 .. +31
    const int nw   = wid & 1;       // 0..1 : code cols nw*128 within 256-chunk

    const int n0  = blockIdx.x * M_TILE;
    const int bb  = n0 >> 12;
    const int hw0 = n0 & (HW - 1);
    const float* zb = z + (size_t)bb * CDIM * HW + hw0;

    const uint32_t bh_off[2] = { OFF_BH0, OFF_BH1 };

    // prologue: cp.async chunk 0 (hi + esq tail)
    {
        #pragma unroll
        for (int t = 0; t < 8; t++) {
            int item = tid + 256 * t;          // 0..2047
            int row  = item >> 3;
            int part = item & 7;
            cp16(sb + OFF_BH0 + row * B_STRIDE + part * 16, g_embh + row * 64 + part * 8);
        }
        if (tid < 64)
            cp16(sb + OFF_BH0 + ESQ_TAIL + tid * 16, g_esq + tid * 4);
        cp_commit();
    }

    // stage z (scaled, hi only) into A tile
    #pragma unroll
    for (int t = 0; t < 16; t++) {
        int i   = tid + 256 * t;
        int c2  = (i >> 7) * 2;
        int tok = i & 127;
        float v0 = zb[(size_t)c2 * HW + tok] * SCALE;
        float v1 = zb[(size_t)(c2 + 1) * HW + tok] * SCALE;
        *(uint32_t*)(sm + OFF_AH + tok * B_STRIDE + c2 * 2) = pack2h(v0, v1);
    }
    cp_wait<0>();
    __syncthreads();

    // ldmatrix lane address pieces
    const int arow  = (lane & 7) + ((lane >> 3) & 1) * 8;
    const int akoff = ((lane >> 4) & 1) * 16;
    const int brow  = (lane & 7) + ((lane >> 4) & 1) * 8;
    const int bkoff = ((lane >> 3) & 1) * 16;

    // A fragments persistent in registers: two m16 tiles (m32 total)
    uint32_t Ah[2][4][4];
    {
        const uint32_t ahad = sb + OFF_AH + (uint32_t)(mg * 32 + arow) * B_STRIDE + akoff;
        #pragma unroll
        for (int s = 0; s < 4; s++) {
            ldmx4(Ah[0][s][0], Ah[0][s][1], Ah[0][s][2], Ah[0][s][3], ahad + s * 32);
            ldmx4(Ah[1][s][0], Ah[1][s][1], Ah[1][s][2], Ah[1][s][3],
                  ahad + 16 * B_STRIDE + s * 32);
        }
    }

    for (int ch = 0; ch < NCHUNKS; ch++) {
        const int buf = ch & 1;

        if (ch < NCHUNKS - 1) {
            const size_t cbase = (size_t)(ch + 1) * N_CHUNK * CDIM;
            #pragma unroll
            for (int t = 0; t < 8; t++) {
                int item = tid + 256 * t;
                int row  = item >> 3;
                int part = item & 7;
                cp16(sb + bh_off[buf ^ 1] + row * B_STRIDE + part * 16,
                     g_embh + cbase + row * 64 + part * 8);
            }
            if (tid < 64)
                cp16(sb + bh_off[buf ^ 1] + ESQ_TAIL + tid * 16,
                     g_esq + (ch + 1) * N_CHUNK + tid * 4);
            cp_commit();
            cp_wait<1>();
        } else {
            cp_wait<0>();
        }
        __syncthreads();

        const float* esq_t = (const float*)(sm + bh_off[buf] + ESQ_TAIL);

        float gmn[4];   // carried across step parity (16-code group merge)

        // ---- 4 n32 steps over this warp's 128-code half ----
        #pragma unroll
        for (int step = 0; step < 4; step++) {
            const int nbase = nw * 128 + step * 32;
            const uint32_t bhb = sb + bh_off[buf] + (uint32_t)(nbase + brow) * B_STRIDE + bkoff;

            float acc[2][4][4];
            #pragma unroll
            for (int m = 0; m < 2; m++)
                #pragma unroll
                for (int f = 0; f < 4; f++)
                    #pragma unroll
                    for (int r = 0; r < 4; r++) acc[m][f][r] = 0.f;

            #pragma unroll
            for (int s = 0; s < 4; s++) {
                uint32_t h0, h1, h2, h3, h4, h5, h6, h7;
                ldmx4(h0, h1, h2, h3, bhb + s * 32);
                ldmx4(h4, h5, h6, h7, bhb + 16 * B_STRIDE + s * 32);
                mma16816(acc[0][0], Ah[0][s], h0, h1);
                mma16816(acc[0][1], Ah[0][s], h2, h3);
                mma16816(acc[1][0], Ah[1][s], h0, h1);
                mma16816(acc[1][1], Ah[1][s], h2, h3);
                mma16816(acc[0][2], Ah[0][s], h4, h5);
                mma16816(acc[0][3], Ah[0][s], h6, h7);
                mma16816(acc[1][2], Ah[1][s], h4, h5);
                mma16816(acc[1][3], Ah[1][s], h6, h7);
            }

            // epilogue: scores (descaled), min over 8, merge step-pairs into 16-groups
            float2 ee[4];
            #pragma unroll
            for (int f = 0; f < 4; f++)
                ee[f] = *(const float2*)&esq_t[nbase + f * 8 + 2 * tid4];

            const int sph = step >> 1, par = step & 1;
            #pragma unroll
            for (int g = 0; g < 4; g++) {   // token = mg*32 + (g>>1)*16 + (g&1)*8 + grp
                const int m = g >> 1, h = g & 1;
                float sv[8];
                #pragma unroll
                for (int f = 0; f < 4; f++) {
                    sv[2 * f]     = fmaf(acc[m][f][h * 2 + 0], NEG2DESC, ee[f].x);
                    sv[2 * f + 1] = fmaf(acc[m][f][h * 2 + 1], NEG2DESC, ee[f].y);
                }
                float m01 = fminf(sv[0], sv[1]), m23 = fminf(sv[2], sv[3]);
                float m45 = fminf(sv[4], sv[5]), m67 = fminf(sv[6], sv[7]);
                float mn = fminf(fminf(m01, m23), fminf(m45, m67));
                if (par == 0) {
                    gmn[g] = mn;
                } else {
                    float mm = fminf(gmn[g], mn);
                    int tok = mg * 32 + m * 16 + h * 8 + grp;
                    int col16 = (nw * 2 + sph) * 4 + tid4;
                    *(__half*)(sm + OFF_SB + tok * 48 + col16 * 2) = __float2half_rn(mm);
                }
            }
        }
        __syncthreads();

        // dump 16 gid-cols x 128 tokens to gmem, coalesced
        {
            int tok = tid >> 1, hf = tid & 1;
            uint4 x = *(const uint4*)(sm + OFF_SB + tok * 48 + hf * 16);
            *(uint4*)(g_smin + (size_t)(n0 + tok) * 256 + ch * 16 + hf * 8) = x;
        }
        __syncthreads();
    }
}

// ---- stage 2: certified resolve + exact rescore + gather ----
__global__ __launch_bounds__(THREADS, 3)
void vq_resolve(const float* __restrict__ z,
                const float* __restrict__ emb,
                float* __restrict__ out) {
    extern __shared__ char sm[];
    float* zs    = (float*)sm;               // [64][130] natural z
    int*   sidx  = (int*)(sm + 33280);       // [128]
    float* eps_s = (float*)(sm + 33792);     // [128] per-token window

    const int tid  = threadIdx.x;
    const int lane = tid & 31;
    const int wid  = tid >> 5;

    const int n0  = blockIdx.x * M_TILE;
    const int bb  = n0 >> 12;
    const int hw0 = n0 & (HW - 1);
    const float* zb = z + (size_t)bb * CDIM * HW + hw0;

    #pragma unroll
    for (int t = 0; t < 32; t++) {
        int i = tid + 256 * t;
        int c = i >> 7, tok = i & 127;
        zs[c * 130 + tok] = zb[(size_t)c * HW + tok];
    }
    __syncthreads();

    // prepass: per-token certified window, thread-per-token
    if (tid < 128) {
        const int t = tid;
        const float Eh2 = __int_as_float(g_Eh2);
        const float El2 = __int_as_float(g_El2);
        float hz = 0.f, lz = 0.f;
        #pragma unroll
        for (int c = 0; c < 64; c++) {
            float v = zs[c * 130 + t] * SCALE;
            float h = __half2float(__float2half_rn(v));
            float l = v - h;
            hz = fmaf(h, h, hz);
            lz = fmaf(l, l, lz);
        }
        float eps_dot = sqrtf(lz * Eh2) + sqrtf(hz * El2) + sqrtf(lz * El2);
        eps_s[t] = eps_dot * (4.0f * DESC) + 0.5f;
    }
    __syncthreads();

    // software-pipelined token loop: prefetch next token's group mins
    uint4 nx = ((const uint4*)(g_smin + (size_t)(n0 + wid * 16) * 256))[lane];

    for (int tt = 0; tt < 16; tt++) {
        const int t = wid * 16 + tt;
        uint4 cur = nx;
        if (tt < 15)
            nx = ((const uint4*)(g_smin + (size_t)(n0 + t + 1) * 256))[lane];

        float hv[8];
        {
            uint32_t w[4] = { cur.x, cur.y, cur.z, cur.w };
            #pragma unroll
            for (int j = 0; j < 4; j++) {
                float2 f = __half22float2(*(__half2*)&w[j]);
                hv[2 * j] = f.x; hv[2 * j + 1] = f.y;
            }
        }
        float m = hv[0];
        #pragma unroll
        for (int j = 1; j < 8; j++) m = fminf(m, hv[j]);
        #pragma unroll
        for (int off = 16; off; off >>= 1)
            m = fminf(m, __shfl_xor_sync(0xffffffffu, m, off));

        const float thr = m + eps_s[t];

        float bv = FLT_MAX;
        int   bc = 0x7fffffff;
        const int kq = lane & 3;
        const int fsel = ((lane >> 3) << 3) + ((lane >> 2) & 1);  // f*8 + p

        #pragma unroll
        for (int i = 0; i < 8; i++) {
            unsigned mb = __ballot_sync(0xffffffffu, hv[i] <= thr);
            while (mb) {
                int src = __ffs(mb) - 1;
                mb &= mb - 1;
                int gid  = src * 8 + i;
                int base = (gid >> 2) * 64 + 2 * (gid & 3);
                #pragma unroll
                for (int sub = 0; sub < 2; sub++) {
                    int code = base + sub * 32 + fsel;
                    const float4* e4 = (const float4*)(emb + (size_t)code * CDIM) + kq * 4;
                    float dot = 0.f;
                    #pragma unroll
                    for (int j = 0; j < 4; j++) {
                        float4 e = __ldg(&e4[j]);
                        int k = kq * 16 + j * 4;
                        dot = fmaf(zs[(k + 0) * 130 + t], e.x, dot);
                        dot = fmaf(zs[(k + 1) * 130 + t], e.y, dot);
                        dot = fmaf(zs[(k + 2) * 130 + t], e.z, dot);
                        dot = fmaf(zs[(k + 3) * 130 + t], e.w, dot);
                    }
                    dot += __shfl_xor_sync(0xffffffffu, dot, 1);
                    dot += __shfl_xor_sync(0xffffffffu, dot, 2);
                    float d = fmaf(dot, -2.0f, g_esq[code]);
                    int   c = code;
                    #pragma unroll
                    for (int off = 4; off <= 16; off <<= 1) {
                        float od = __shfl_xor_sync(0xffffffffu, d, off);
                        int   oc = __shfl_xor_sync(0xffffffffu, c, off);
                        if (od < d || (od == d && oc < c)) { d = od; c = oc; }
                    }
                    if (d < bv || (d == bv && c < bc)) { bv = d; bc = c; }
                }
            }
        }
        if (lane == 0) sidx[t] = bc;
    }
    __syncthreads();

    // gather emb[idx], transposed coalesced write (stage over zs)
    float* st = zs;   // [128][65]
    #pragma unroll
    for (int t = 0; t < 32; t++) {
        int i = tid + 256 * t;
        int tok = i >> 6, c = i & 63;
        st[tok * 65 + c] = emb[(size_t)sidx[tok] * CDIM + c];
    }
    __syncthreads();
    float* ob = out + (size_t)bb * CDIM * HW + hw0;
    #pragma unroll
    for (int t = 0; t < 32; t++) {
        int i = tid + 256 * t;
        int c = i >> 7, tok = i & 127;
        ob[(size_t)c * HW + tok] = st[tok * 65 + c];
    }
}

extern "C" void kernel_launch(void* const* d_in, const int* in_sizes, int n_in,
                              void* d_out, int out_size) {
    const float* z   = (const float*)d_in[0];
    const float* emb = (const float*)d_in[1];
    float* out = (float*)d_out;

    cudaFuncSetAttribute(vq_main, cudaFuncAttributeMaxDynamicSharedMemorySize, SMEM_MAIN);
    cudaFuncSetAttribute(vq_resolve, cudaFuncAttributeMaxDynamicSharedMemorySize, SMEM_RES);

    prep_kernel<<<NCODES / 8, 256>>>(emb);
    vq_main<<<NTOK / M_TILE, THREADS, SMEM_MAIN>>>(z);
    vq_resolve<<<NTOK / M_TILE, THREADS, SMEM_RES>>>(z, emb, out);
}